// round 1
// baseline (speedup 1.0000x reference)
#include <cuda_runtime.h>
#include <math.h>

#define DD 128
#define NPAD 100096

// Scratch (device globals: no allocation allowed)
static __device__ float g_hW  [(size_t)NPAD * DD];   // 51.2 MB
static __device__ float g_agg [(size_t)NPAD * DD];   // 51.2 MB
static __device__ float g_G1  [(size_t)NPAD * 384];  // 153.7 MB  (gx)
static __device__ float g_G2  [(size_t)NPAD * 384];  // 153.7 MB  (gh)
static __device__ float g_WihT[256 * 384];
static __device__ float g_WhhT[128 * 384];

// ---------------------------------------------------------------------------
// Weight transpose: WihT[k][j] = w_ih[j][k] (j<384,k<256); WhhT likewise.
// ---------------------------------------------------------------------------
__global__ __launch_bounds__(256) void prep_weights(const float* __restrict__ w_ih,
                                                    const float* __restrict__ w_hh) {
    int tid = blockIdx.x * 256 + threadIdx.x;
    if (tid < 256 * 384) {
        int k = tid / 384, j = tid - k * 384;
        g_WihT[tid] = w_ih[j * 256 + k];
    } else {
        int t2 = tid - 256 * 384;
        if (t2 < 128 * 384) {
            int k = t2 / 384, j = t2 - k * 384;
            g_WhhT[t2] = w_hh[j * 128 + k];
        }
    }
}

// ---------------------------------------------------------------------------
// GEMM A: hW[m][:] = ent[nid[m]][:] @ W   (M x 128 x 128)
// 128x128 tile, BK=16, 256 threads, 8x8 microtile.
// ---------------------------------------------------------------------------
__global__ __launch_bounds__(256) void gemmA(const float* __restrict__ ent,
                                             const int*   __restrict__ nid,
                                             const float* __restrict__ W, int M) {
    __shared__ float As[16][132];
    __shared__ float Bs[16][132];
    const int tid  = threadIdx.x;
    const int m0   = blockIdx.x * 128;
    const int arow = tid >> 1;
    const int kseg = (tid & 1) * 8;
    const int m    = m0 + arow;
    const float* arowp = (m < M) ? ent + (size_t)nid[m] * DD : (const float*)0;

    const int ty = tid >> 4, tx = tid & 15;
    float acc[8][8];
#pragma unroll
    for (int i = 0; i < 8; i++)
#pragma unroll
        for (int j = 0; j < 8; j++) acc[i][j] = 0.f;

    for (int kt = 0; kt < 8; kt++) {
        float av[8];
        if (arowp) {
            float4 a0 = *(const float4*)(arowp + kt * 16 + kseg);
            float4 a1 = *(const float4*)(arowp + kt * 16 + kseg + 4);
            av[0]=a0.x; av[1]=a0.y; av[2]=a0.z; av[3]=a0.w;
            av[4]=a1.x; av[5]=a1.y; av[6]=a1.z; av[7]=a1.w;
        } else {
#pragma unroll
            for (int i = 0; i < 8; i++) av[i] = 0.f;
        }
#pragma unroll
        for (int i = 0; i < 8; i++) As[kseg + i][arow] = av[i];
#pragma unroll
        for (int i = 0; i < 2; i++) {
            int idx = tid * 2 + i;
            int r = idx >> 5, c = (idx & 31) * 4;
            float4 v = *(const float4*)(W + (kt * 16 + r) * DD + c);
            Bs[r][c] = v.x; Bs[r][c+1] = v.y; Bs[r][c+2] = v.z; Bs[r][c+3] = v.w;
        }
        __syncthreads();
#pragma unroll
        for (int k = 0; k < 16; k++) {
            float a[8], b[8];
#pragma unroll
            for (int i = 0; i < 8; i++) a[i] = As[k][ty * 8 + i];
#pragma unroll
            for (int j = 0; j < 8; j++) b[j] = Bs[k][tx * 8 + j];
#pragma unroll
            for (int i = 0; i < 8; i++)
#pragma unroll
                for (int j = 0; j < 8; j++) acc[i][j] = fmaf(a[i], b[j], acc[i][j]);
        }
        __syncthreads();
    }
#pragma unroll
    for (int i = 0; i < 8; i++) {
        int mm = m0 + ty * 8 + i;
        if (mm < M) {
            *(float4*)&g_hW[(size_t)mm * DD + tx * 8]     = make_float4(acc[i][0], acc[i][1], acc[i][2], acc[i][3]);
            *(float4*)&g_hW[(size_t)mm * DD + tx * 8 + 4] = make_float4(acc[i][4], acc[i][5], acc[i][6], acc[i][7]);
        }
    }
}

// ---------------------------------------------------------------------------
// Edge scatter: one warp per edge; agg[dst] += hW[src], 128 floats per edge,
// vectorized f32x4 reduction (sm_90+).
// ---------------------------------------------------------------------------
__global__ __launch_bounds__(256) void scatter_edges(const int* __restrict__ src,
                                                     const int* __restrict__ dst, int E) {
    int gw   = (blockIdx.x * 256 + threadIdx.x) >> 5;
    int lane = threadIdx.x & 31;
    if (gw >= E) return;
    int s = __ldg(&src[gw]);
    int d = __ldg(&dst[gw]);
    float4 v = *((const float4*)(g_hW + (size_t)s * DD) + lane);
    float* addr = g_agg + (size_t)d * DD + lane * 4;
    asm volatile("red.global.add.v4.f32 [%0], {%1,%2,%3,%4};"
                 :: "l"(addr), "f"(v.x), "f"(v.y), "f"(v.z), "f"(v.w) : "memory");
}

// ---------------------------------------------------------------------------
// GEMM G: C[m][c0:c0+128] = sum_k A(m,k) * Bt[k][c]
// Two K-phases: phase0 = A0 row * rowscale (nkt0*16 k's), phase1 = A1 row.
// Bt is [K_total][384]. Used for gx (A0=agg*out_norm, A1=e_r_bias, Bt=WihT)
// and gh (A0=e_r_bias, Bt=WhhT, nkt1=0).
// ---------------------------------------------------------------------------
__global__ __launch_bounds__(256) void gemmG(const float* __restrict__ A0,
                                             const float* __restrict__ rs,
                                             const float* __restrict__ A1,
                                             const float* __restrict__ Bt,
                                             float* __restrict__ C,
                                             int M, int nkt0, int nkt1) {
    __shared__ float As[16][132];
    __shared__ float Bs[16][132];
    const int tid  = threadIdx.x;
    const int m0   = blockIdx.x * 128;
    const int c0   = blockIdx.y * 128;
    const int arow = tid >> 1;
    const int kseg = (tid & 1) * 8;
    const int m    = m0 + arow;
    const bool mval = (m < M);
    const float scale = (mval && rs) ? rs[m] : 1.f;
    const float* a0p = mval ? A0 + (size_t)m * DD : (const float*)0;
    const float* a1p = (mval && A1) ? A1 + (size_t)m * DD : (const float*)0;

    const int ty = tid >> 4, tx = tid & 15;
    float acc[8][8];
#pragma unroll
    for (int i = 0; i < 8; i++)
#pragma unroll
        for (int j = 0; j < 8; j++) acc[i][j] = 0.f;

    const int nkt = nkt0 + nkt1;
    for (int kt = 0; kt < nkt; kt++) {
        const float* ap; float sc; int koff;
        if (kt < nkt0) { ap = a0p; sc = scale; koff = kt * 16; }
        else           { ap = a1p; sc = 1.f;   koff = (kt - nkt0) * 16; }
        float av[8];
        if (ap) {
            float4 a0v = *(const float4*)(ap + koff + kseg);
            float4 a1v = *(const float4*)(ap + koff + kseg + 4);
            av[0]=a0v.x*sc; av[1]=a0v.y*sc; av[2]=a0v.z*sc; av[3]=a0v.w*sc;
            av[4]=a1v.x*sc; av[5]=a1v.y*sc; av[6]=a1v.z*sc; av[7]=a1v.w*sc;
        } else {
#pragma unroll
            for (int i = 0; i < 8; i++) av[i] = 0.f;
        }
#pragma unroll
        for (int i = 0; i < 8; i++) As[kseg + i][arow] = av[i];
#pragma unroll
        for (int i = 0; i < 2; i++) {
            int idx = tid * 2 + i;
            int r = idx >> 5, c = (idx & 31) * 4;
            float4 v = *(const float4*)(Bt + (size_t)(kt * 16 + r) * 384 + c0 + c);
            Bs[r][c] = v.x; Bs[r][c+1] = v.y; Bs[r][c+2] = v.z; Bs[r][c+3] = v.w;
        }
        __syncthreads();
#pragma unroll
        for (int k = 0; k < 16; k++) {
            float a[8], b[8];
#pragma unroll
            for (int i = 0; i < 8; i++) a[i] = As[k][ty * 8 + i];
#pragma unroll
            for (int j = 0; j < 8; j++) b[j] = Bs[k][tx * 8 + j];
#pragma unroll
            for (int i = 0; i < 8; i++)
#pragma unroll
                for (int j = 0; j < 8; j++) acc[i][j] = fmaf(a[i], b[j], acc[i][j]);
        }
        __syncthreads();
    }
#pragma unroll
    for (int i = 0; i < 8; i++) {
        int mm = m0 + ty * 8 + i;
        if (mm < M) {
            *(float4*)&C[(size_t)mm * 384 + c0 + tx * 8]     = make_float4(acc[i][0], acc[i][1], acc[i][2], acc[i][3]);
            *(float4*)&C[(size_t)mm * 384 + c0 + tx * 8 + 4] = make_float4(acc[i][4], acc[i][5], acc[i][6], acc[i][7]);
        }
    }
}

// ---------------------------------------------------------------------------
// GRU gates + ReLU + L2 normalize. One warp per node, 4 dims per lane.
// ---------------------------------------------------------------------------
__device__ __forceinline__ float sigmoidf_(float x) { return 1.f / (1.f + __expf(-x)); }

__global__ __launch_bounds__(256) void gru_norm(const float* __restrict__ hbias,
                                                const float* __restrict__ b_ih,
                                                const float* __restrict__ b_hh,
                                                float* __restrict__ out, int M) {
    int w    = (blockIdx.x * 256 + threadIdx.x) >> 5;
    int lane = threadIdx.x & 31;
    if (w >= M) return;
    const float* g1 = g_G1 + (size_t)w * 384;
    const float* g2 = g_G2 + (size_t)w * 384;
    int j = lane * 4;
    float4 xr  = *(const float4*)(g1 + j);
    float4 xz  = *(const float4*)(g1 + 128 + j);
    float4 xn  = *(const float4*)(g1 + 256 + j);
    float4 hr  = *(const float4*)(g2 + j);
    float4 hz  = *(const float4*)(g2 + 128 + j);
    float4 hn  = *(const float4*)(g2 + 256 + j);
    float4 hh  = *(const float4*)(hbias + (size_t)w * DD + j);
    float4 bir = *(const float4*)(b_ih + j);
    float4 biz = *(const float4*)(b_ih + 128 + j);
    float4 bin_= *(const float4*)(b_ih + 256 + j);
    float4 bhr = *(const float4*)(b_hh + j);
    float4 bhz = *(const float4*)(b_hh + 128 + j);
    float4 bhn = *(const float4*)(b_hh + 256 + j);

    float ss = 0.f; float4 res;
#define GRU1(c) { \
    float rg = sigmoidf_(xr.c + bir.c + hr.c + bhr.c); \
    float zg = sigmoidf_(xz.c + biz.c + hz.c + bhz.c); \
    float ng = tanhf(xn.c + bin_.c + rg * (hn.c + bhn.c)); \
    float hv = (1.f - zg) * ng + zg * hh.c; \
    hv = fmaxf(hv, 0.f); \
    res.c = hv; ss += hv * hv; }
    GRU1(x) GRU1(y) GRU1(z) GRU1(w)
#undef GRU1
#pragma unroll
    for (int off = 16; off; off >>= 1) ss += __shfl_xor_sync(0xffffffffu, ss, off);
    float inv = 1.f / fmaxf(sqrtf(ss), 1e-12f);
    res.x *= inv; res.y *= inv; res.z *= inv; res.w *= inv;
    *(float4*)(out + (size_t)w * DD + j) = res;
}

// ---------------------------------------------------------------------------
extern "C" void kernel_launch(void* const* d_in, const int* in_sizes, int n_in,
                              void* d_out, int out_size) {
    const float* ent   = (const float*)d_in[0];
    // d_in[1] = rel_embs (unused by reference)
    const float* e_r   = (const float*)d_in[2];
    const float* onorm = (const float*)d_in[3];
    const float* W     = (const float*)d_in[4];
    const float* w_ih  = (const float*)d_in[5];
    const float* w_hh  = (const float*)d_in[6];
    const float* b_ih  = (const float*)d_in[7];
    const float* b_hh  = (const float*)d_in[8];
    const int*   nid   = (const int*)d_in[9];
    const int*   esrc  = (const int*)d_in[10];
    const int*   edst  = (const int*)d_in[11];
    const int M = in_sizes[2] / DD;
    const int E = in_sizes[10];
    float* out = (float*)d_out;

    void* pv;
    cudaGetSymbolAddress(&pv, g_agg);   float* aggp  = (float*)pv;
    cudaGetSymbolAddress(&pv, g_WihT);  float* wihtp = (float*)pv;
    cudaGetSymbolAddress(&pv, g_WhhT);  float* whhtp = (float*)pv;
    cudaGetSymbolAddress(&pv, g_G1);    float* g1p   = (float*)pv;
    cudaGetSymbolAddress(&pv, g_G2);    float* g2p   = (float*)pv;

    cudaMemsetAsync(aggp, 0, (size_t)M * DD * sizeof(float), 0);
    prep_weights<<<576, 256>>>(w_ih, w_hh);
    gemmA<<<(M + 127) / 128, 256>>>(ent, nid, W, M);
    scatter_edges<<<(E + 7) / 8, 256>>>(esrc, edst, E);
    dim3 gg((M + 127) / 128, 3);
    // gx = [agg*out_norm, e_r_bias] @ WihT
    gemmG<<<gg, 256>>>(aggp, onorm, e_r, wihtp, g1p, M, 8, 8);
    // gh = e_r_bias @ WhhT
    gemmG<<<gg, 256>>>(e_r, (const float*)0, (const float*)0, whhtp, g2p, M, 8, 0);
    gru_norm<<<(M + 7) / 8, 256>>>(e_r, b_ih, b_hh, out, M);
}